// round 13
// baseline (speedup 1.0000x reference)
#include <cuda_runtime.h>
#include <math.h>

#define THREADS 256
#define STAGES  8                       // ring depth; STAGES-2 tiles in flight
#define CPT     THREADS                 // chunks (16B) per tile = 1 per thread
#define GRID    1036                    // 148 SMs * 7 resident CTAs

__device__ unsigned int g_row;          // next row to process (memset to 0 per launch)

__device__ __forceinline__ void cp_async16(void* smem_dst, const void* gsrc) {
    unsigned saddr = (unsigned)__cvta_generic_to_shared(smem_dst);
    asm volatile("cp.async.cg.shared.global [%0], [%1], 16;\n"
                 :: "r"(saddr), "l"(gsrc));
}
__device__ __forceinline__ void cp_async_commit() {
    asm volatile("cp.async.commit_group;\n" ::: "memory");
}
template<int N>
__device__ __forceinline__ void cp_async_wait() {
    asm volatile("cp.async.wait_group %0;\n" :: "n"(N) : "memory");
}

__global__ __launch_bounds__(THREADS)
void wrpl_row_kernel(const float* __restrict__ scores,
                     const int* __restrict__ targets,
                     float* __restrict__ out,
                     int B, int C)
{
    // Per-thread 16B slots -> no cross-thread smem sharing -> no barriers in
    // the streaming loop; cp.async.wait_group orders each thread's write/read.
    __shared__ float4 buf[STAGES][CPT];          // 32 KB
    __shared__ int    sh_row;
    __shared__ int    sh_rk [THREADS / 32];
    __shared__ int    sh_pos[THREADS / 32];
    __shared__ float  sh_xs [THREADS / 32];

    const int td   = threadIdx.x;
    const int lane = td & 31;
    const int wid  = td >> 5;
    const unsigned FULL = 0xFFFFFFFFu;

    const int nChunks = C >> 2;                  // C % 4 == 0
    const int nTiles  = (nChunks + CPT - 1) / CPT;

    for (;;) {
        // ---- dynamic row fetch ----
        if (td == 0)
            sh_row = (int)atomicAdd(&g_row, 1u);
        __syncthreads();
        const int row = sh_row;
        if (row >= B) break;
        __syncthreads();                         // protect sh_row before next write

        const float* s = scores + (size_t)row * (size_t)C;
        const int t  = targets[row];
        const float gt  = __ldg(s + t);
        const float thr = gt - 1.0f;             // hinge: l > 0 <=> x > gt-1
        const int tb = t >> 2;                   // chunk containing j == t

        const float4* s4 = reinterpret_cast<const float4*>(s);

        int   cnt_rank = 0;   // #{j<t: s_j >= gt} + #{j>t: s_j > gt} = rank-1
        int   cnt_pos  = 0;   // #{j != t : s_j > thr}
        float xsum     = 0.0f;

        // ---- prologue: fill STAGES-2 stages ----
        cp_async_wait<0>();                      // drain any previous row's groups
        #pragma unroll
        for (int pt = 0; pt < STAGES - 2; ++pt) {
            int c4 = pt * CPT + td;
            if (pt < nTiles && c4 < nChunks)
                cp_async16(&buf[pt][td], s4 + c4);
            cp_async_commit();
        }

#define PROC_GE(xv) { float x = (xv); cnt_rank += (x >= gt); bool p = (x > thr); cnt_pos += p; if (p) xsum += x; }
#define PROC_GT(xv) { float x = (xv); cnt_rank += (x >  gt); bool p = (x > thr); cnt_pos += p; if (p) xsum += x; }

        // ---- streaming loop: 1 issue + 1 wait per tile, no barriers ----
        for (int tile = 0; tile < nTiles; ++tile) {
            const int it = tile + STAGES - 2;
            if (it < nTiles) {
                int c4i = it * CPT + td;
                if (c4i < nChunks)
                    cp_async16(&buf[it % STAGES][td], s4 + c4i);
            }
            cp_async_commit();
            cp_async_wait<STAGES - 2>();         // own tile `tile` complete

            const int c4 = tile * CPT + td;
            if (c4 < nChunks) {
                float4 v = buf[tile % STAGES][td];
                if (c4 < tb) {                   // all idx < t
                    PROC_GE(v.x) PROC_GE(v.y) PROC_GE(v.z) PROC_GE(v.w)
                } else if (c4 > tb) {            // all idx > t
                    PROC_GT(v.x) PROC_GT(v.y) PROC_GT(v.z) PROC_GT(v.w)
                } else {                         // boundary chunk: has j == t
                    const float xv[4] = {v.x, v.y, v.z, v.w};
                    const int base = c4 << 2;
                    #pragma unroll
                    for (int e = 0; e < 4; ++e) {
                        int idx = base + e;
                        if (idx == t) continue;
                        float x = xv[e];
                        cnt_rank += (idx < t) ? (x >= gt) : (x > gt);
                        bool p = (x > thr);
                        cnt_pos += p;
                        if (p) xsum += x;
                    }
                }
            }
        }
#undef PROC_GE
#undef PROC_GT

        // ---- block reduction ----
        #pragma unroll
        for (int off = 16; off > 0; off >>= 1) {
            cnt_rank += __shfl_down_sync(FULL, cnt_rank, off);
            cnt_pos  += __shfl_down_sync(FULL, cnt_pos,  off);
            xsum     += __shfl_down_sync(FULL, xsum,     off);
        }
        if (lane == 0) {
            sh_rk[wid]  = cnt_rank;
            sh_pos[wid] = cnt_pos;
            sh_xs[wid]  = xsum;
        }
        __syncthreads();

        if (td == 0) {
            int   rk = 0, p = 0;
            float xs = 0.0f;
            #pragma unroll
            for (int i = 0; i < THREADS / 32; i++) {
                rk += sh_rk[i]; p += sh_pos[i]; xs += sh_xs[i];
            }

            const int rank = rk + 1;
            const float hinge = xs - (float)p * thr;

            // harmonic number H(rank)
            double H;
            if (rank <= 64) {
                H = 0.0;
                for (int i = 1; i <= rank; i++) H += 1.0 / (double)i;
            } else {
                double n  = (double)rank;
                double n2 = n * n;
                H = log(n) + 0.57721566490153286
                  + 1.0 / (2.0 * n) - 1.0 / (12.0 * n2) + 1.0 / (120.0 * n2 * n2);
            }

            float npos = (float)p + 1e-7f;
            float loss = (float)H / npos * hinge;
            atomicAdd(out, loss / (float)B);
        }
        __syncthreads();                         // sh_* reuse safe for next row
    }
}

extern "C" void kernel_launch(void* const* d_in, const int* in_sizes, int n_in,
                              void* d_out, int out_size)
{
    const float* scores  = (const float*)d_in[0];
    const int*   targets = (const int*)d_in[1];
    float*       out     = (float*)d_out;

    const int B = in_sizes[1];
    const int C = in_sizes[0] / B;

    static void* ctr_ptr = nullptr;
    if (!ctr_ptr)
        cudaGetSymbolAddress(&ctr_ptr, g_row);

    cudaMemsetAsync(out, 0, sizeof(float));      // graph memset nodes
    cudaMemsetAsync(ctr_ptr, 0, sizeof(unsigned int));
    wrpl_row_kernel<<<GRID, THREADS>>>(scores, targets, out, B, C);
}